// round 11
// baseline (speedup 1.0000x reference)
#include <cuda_runtime.h>
#include <cuda_fp16.h>
#include <cstdint>

// AFT-Full simplified: exp_pos_bias == 1  =>  num/den are per-(b,d) sums over t.
// out = ( sigmoid(q@WqT) * num/den ) @ WoT
// GEMMs: legacy mma.sync fp16 single-term, 128x128 tiles, 256 thr, 2 CTAs/SM,
// BK=64, XOR-swizzled smem. This round: whole-tile B-fragment preload
// (register-budgeted software pipelining) + gmem-direct epilogue ratios.

#define BB 4
#define TT 2048
#define DD 1024
#define MTOT (BB * TT)   // 8192
#define KD 1024

// ---------------- scratch (static device globals) ----------------
__device__ __half g_qh[MTOT * KD];
__device__ __half g_kh[MTOT * KD];
__device__ __half g_vh[MTOT * KD];
__device__ __half g_Wqh[DD * KD], g_Wkh[DD * KD], g_Wvh[DD * KD], g_Woh[DD * KD];
__device__ __half g_Yth[MTOT * DD];
__device__ __half g_Kph[MTOT * DD];
__device__ __half g_Vph[MTOT * DD];
__device__ float g_num[BB * DD];
__device__ float g_den[BB * DD];

// ---------------- merged fp32 -> fp16 convert, all 7 tensors ----------------
constexpr int ACT_CH = MTOT * KD / 16;   // 524288 chunks of 16 floats
constexpr int W_CH   = DD * KD / 16;     // 65536
constexpr int TOT_CH = 3 * ACT_CH + 4 * W_CH;

__global__ __launch_bounds__(256) void convert_all(
    const float* __restrict__ q, const float* __restrict__ k, const float* __restrict__ v,
    const float* __restrict__ wq, const float* __restrict__ wk,
    const float* __restrict__ wv, const float* __restrict__ wo)
{
    const int i = blockIdx.x * blockDim.x + threadIdx.x;

    if (i < BB * DD) { g_num[i] = 0.0f; g_den[i] = 0.0f; }

    const float* src;
    __half* dst;
    size_t off;
    if (i < ACT_CH)              { src = q;  dst = g_qh;  off = i; }
    else if (i < 2 * ACT_CH)     { src = k;  dst = g_kh;  off = i - ACT_CH; }
    else if (i < 3 * ACT_CH)     { src = v;  dst = g_vh;  off = i - 2 * ACT_CH; }
    else {
        int w = i - 3 * ACT_CH;
        int t = w >> 16;
        off = w & 65535;
        if (t == 0)      { src = wq; dst = g_Wqh; }
        else if (t == 1) { src = wk; dst = g_Wkh; }
        else if (t == 2) { src = wv; dst = g_Wvh; }
        else             { src = wo; dst = g_Woh; }
    }

    const float4* s4 = (const float4*)(src) + off * 4;
    float4 x0 = s4[0], x1 = s4[1], x2 = s4[2], x3 = s4[3];
    float xs[16] = {x0.x, x0.y, x0.z, x0.w, x1.x, x1.y, x1.z, x1.w,
                    x2.x, x2.y, x2.z, x2.w, x3.x, x3.y, x3.z, x3.w};
    __half h[16];
#pragma unroll
    for (int j = 0; j < 16; j++) h[j] = __float2half(xs[j]);
    uint4* d4 = (uint4*)(dst + off * 16);
    d4[0] = *(uint4*)(h);
    d4[1] = *(uint4*)(h + 8);
}

// ---------------- PTX helpers ----------------
__device__ __forceinline__ void ldsm_x4(uint32_t& r0, uint32_t& r1, uint32_t& r2, uint32_t& r3, uint32_t addr) {
    asm volatile("ldmatrix.sync.aligned.m8n8.x4.shared.b16 {%0,%1,%2,%3}, [%4];"
                 : "=r"(r0), "=r"(r1), "=r"(r2), "=r"(r3) : "r"(addr));
}
__device__ __forceinline__ void mma_f16(float* d, const uint32_t* a, const uint32_t* b) {
    asm volatile("mma.sync.aligned.m16n8k16.row.col.f32.f16.f16.f32 "
                 "{%0,%1,%2,%3}, {%4,%5,%6,%7}, {%8,%9}, {%0,%1,%2,%3};"
                 : "+f"(d[0]), "+f"(d[1]), "+f"(d[2]), "+f"(d[3])
                 : "r"(a[0]), "r"(a[1]), "r"(a[2]), "r"(a[3]), "r"(b[0]), "r"(b[1]));
}
__device__ __forceinline__ void cp16(uint32_t s, const void* g) {
    asm volatile("cp.async.cg.shared.global [%0], [%1], 16;" :: "r"(s), "l"(g));
}
__device__ __forceinline__ void cp_commit() {
    asm volatile("cp.async.commit_group;" ::: "memory");
}
template <int N>
__device__ __forceinline__ void cp_wait() {
    asm volatile("cp.async.wait_group %0;" :: "n"(N) : "memory");
}

// ---------------- tensor-core GEMM: C[M,N] = A[M,K] @ B[N,K]^T ----------------
// BM=BN=128, BK=64, 3-stage cp.async, 256 threads (8 warps 2x4, warp 64x32),
// 2 CTAs/SM, Swizzle<3,4,3> smem (128B rows).
// MODE 0: K/V merged -> fp16. MODE 1: Q + fused sigmoid*ratio -> Yt.
// MODE 2: out = Yt @ Wo^T -> fp32.
constexpr int BK = 64;
constexpr int NT = KD / BK;              // 16 k-tiles
constexpr int A_T = 128 * BK * 2;        // 16384 B
constexpr int STAGE_B = 2 * A_T;         // 32768 B (A then B)
constexpr int NSTAGE = 3;
constexpr int SMEM_TOTAL = NSTAGE * STAGE_B;  // 98304 B

template <int MODE>
__global__ __launch_bounds__(256, 2) void hgemm(float* __restrict__ Cout)
{
    extern __shared__ char smem[];
    const uint32_t sb = (uint32_t)__cvta_generic_to_shared(smem);

    const __half *A, *Bh;
    __half* Ch = nullptr;
    float* C = nullptr;
    if (MODE == 0) {
        if (blockIdx.z == 0) { A = g_kh; Bh = g_Wkh; Ch = g_Kph; }
        else                 { A = g_vh; Bh = g_Wvh; Ch = g_Vph; }
    } else if (MODE == 1) {
        A = g_qh; Bh = g_Wqh;
    } else {
        A = g_Yth; Bh = g_Woh; C = Cout;
    }

    const int tid = threadIdx.x;
    const int wid = tid >> 5, lane = tid & 31;
    const int rowBase = blockIdx.y * 128;
    const int colBase = blockIdx.x * 128;

    // 8 warps: 2 (M) x 4 (N); warp tile 64x32
    const int warpM = (wid >> 2) * 64;
    const int warpN = (wid & 3) * 32;

    const int aRowL = warpM + (lane & 15);
    const int aC16  = (lane >> 4);            // 0 or 1
    const int bRowL = warpN + ((lane >> 4) << 3) + (lane & 7);
    const int bC16  = ((lane >> 3) & 1);

    float acc[4][4][4];
#pragma unroll
    for (int m = 0; m < 4; m++)
#pragma unroll
        for (int n = 0; n < 4; n++)
#pragma unroll
            for (int r = 0; r < 4; r++) acc[m][n][r] = 0.0f;

    auto fill_stage = [&](int buf, int k0) {
        const uint32_t stg = sb + buf * STAGE_B;
#pragma unroll
        for (int i = 0; i < 4; i++) {   // A: 1024 chunks of 16B, 4/thread
            const int ch = tid + i * 256;
            const int r = ch >> 3, c = ch & 7;
            const uint32_t so = (uint32_t)(r * 128 + ((c ^ (r & 7)) * 16));
            cp16(stg + so, A + (size_t)(rowBase + r) * KD + k0 + c * 8);
        }
#pragma unroll
        for (int i = 0; i < 4; i++) {   // B: 1024 chunks, 4/thread
            const int ch = tid + i * 256;
            const int r = ch >> 3, c = ch & 7;
            const uint32_t so = (uint32_t)(r * 128 + ((c ^ (r & 7)) * 16));
            cp16(stg + A_T + so, Bh + (size_t)(colBase + r) * KD + k0 + c * 8);
        }
        cp_commit();
    };

    fill_stage(0, 0);
    fill_stage(1, BK);

    for (int kt = 0; kt < NT; kt++) {
        if (kt < NT - 1) cp_wait<1>(); else cp_wait<0>();
        __syncthreads();

        if (kt + 2 < NT) fill_stage((kt + 2) % NSTAGE, (kt + 2) * BK);

        const uint32_t stg = sb + (kt % NSTAGE) * STAGE_B;
        const uint32_t sA = stg;
        const uint32_t sB = stg + A_T;

        // ---- preload ALL B fragments for this k-tile (8 ldsm, 32 regs) ----
        uint32_t bAll[4][4][2];   // [substep][n-frag][reg]
#pragma unroll
        for (int s = 0; s < 4; s++) {
#pragma unroll
            for (int p = 0; p < 2; p++) {
                const int row = bRowL + p * 16;
                const int c16 = (s * 2 + bC16) ^ (row & 7);
                const uint32_t addr = sB + (uint32_t)(row * 128 + c16 * 16);
                ldsm_x4(bAll[s][2 * p][0], bAll[s][2 * p][1],
                        bAll[s][2 * p + 1][0], bAll[s][2 * p + 1][1], addr);
            }
        }

#pragma unroll
        for (int s = 0; s < 4; s++) {   // four k16 sub-steps per BK=64
            uint32_t a[4][4];
#pragma unroll
            for (int mf = 0; mf < 4; mf++) {
                const int row = aRowL + mf * 16;
                const int c16 = (s * 2 + aC16) ^ (row & 7);
                const uint32_t addr = sA + (uint32_t)(row * 128 + c16 * 16);
                ldsm_x4(a[mf][0], a[mf][1], a[mf][2], a[mf][3], addr);
            }
#pragma unroll
            for (int m = 0; m < 4; m++)
#pragma unroll
                for (int n = 0; n < 4; n++)
                    mma_f16(acc[m][n], a[m], bAll[s][n]);
        }
        __syncthreads();
    }

    // ---------------- epilogue ----------------
    const int er = rowBase + warpM + (lane >> 2);
    const int ec = colBase + warpN + (lane & 3) * 2;

    if (MODE == 1) {
        const int b = rowBase >> 11;
#pragma unroll
        for (int n = 0; n < 4; n++) {
            const int c = ec + n * 8;
            const float r0 = g_num[b * DD + c]     / g_den[b * DD + c];
            const float r1 = g_num[b * DD + c + 1] / g_den[b * DD + c + 1];
#pragma unroll
            for (int m = 0; m < 4; m++) {
#pragma unroll
                for (int h = 0; h < 2; h++) {
                    const int r = er + m * 16 + h * 8;
                    float y0 = r0 / (1.0f + __expf(-acc[m][n][h * 2]));
                    float y1 = r1 / (1.0f + __expf(-acc[m][n][h * 2 + 1]));
                    *(__half2*)(g_Yth + (size_t)r * DD + c) =
                        __floats2half2_rn(y0, y1);
                }
            }
        }
    } else if (MODE == 0) {
#pragma unroll
        for (int m = 0; m < 4; m++)
#pragma unroll
            for (int n = 0; n < 4; n++) {
                const int c = ec + n * 8;
#pragma unroll
                for (int h = 0; h < 2; h++) {
                    const int r = er + m * 16 + h * 8;
                    *(__half2*)(Ch + (size_t)r * DD + c) =
                        __floats2half2_rn(acc[m][n][h * 2], acc[m][n][h * 2 + 1]);
                }
            }
    } else {
#pragma unroll
        for (int m = 0; m < 4; m++)
#pragma unroll
            for (int n = 0; n < 4; n++) {
                const int c = ec + n * 8;
#pragma unroll
                for (int h = 0; h < 2; h++) {
                    const int r = er + m * 16 + h * 8;
                    *(float2*)(C + (size_t)r * DD + c) =
                        make_float2(acc[m][n][h * 2], acc[m][n][h * 2 + 1]);
                }
            }
    }
}

// ---------------- num/den reduction (fp16 inputs) ----------------
__global__ __launch_bounds__(128) void reduce_kernel() {
    const int d  = blockIdx.x * 128 + threadIdx.x;
    const int t0 = blockIdx.y * 16;

    float num0 = 0.f, num1 = 0.f, num2 = 0.f, num3 = 0.f;
    float den0 = 0.f, den1 = 0.f, den2 = 0.f, den3 = 0.f;

#pragma unroll 4
    for (int t = t0; t < t0 + 16; t++) {
        const size_t off = (size_t)t * DD + d;
        float k0 = __half2float(g_Kph[off + (size_t)0 * TT * DD]);
        float k1 = __half2float(g_Kph[off + (size_t)1 * TT * DD]);
        float k2 = __half2float(g_Kph[off + (size_t)2 * TT * DD]);
        float k3 = __half2float(g_Kph[off + (size_t)3 * TT * DD]);
        float m = fmaxf(fmaxf(k0, k1), fmaxf(k2, k3));
        float e0 = __expf(k0 - m);
        float e1 = __expf(k1 - m);
        float e2 = __expf(k2 - m);
        float e3 = __expf(k3 - m);
        float v0 = __half2float(g_Vph[off + (size_t)0 * TT * DD]);
        float v1 = __half2float(g_Vph[off + (size_t)1 * TT * DD]);
        float v2 = __half2float(g_Vph[off + (size_t)2 * TT * DD]);
        float v3 = __half2float(g_Vph[off + (size_t)3 * TT * DD]);
        num0 = fmaf(e0, v0, num0);  den0 += e0;
        num1 = fmaf(e1, v1, num1);  den1 += e1;
        num2 = fmaf(e2, v2, num2);  den2 += e2;
        num3 = fmaf(e3, v3, num3);  den3 += e3;
    }

    atomicAdd(&g_num[0 * DD + d], num0);
    atomicAdd(&g_num[1 * DD + d], num1);
    atomicAdd(&g_num[2 * DD + d], num2);
    atomicAdd(&g_num[3 * DD + d], num3);
    atomicAdd(&g_den[0 * DD + d], den0);
    atomicAdd(&g_den[1 * DD + d], den1);
    atomicAdd(&g_den[2 * DD + d], den2);
    atomicAdd(&g_den[3 * DD + d], den3);
}

// ---------------------------------------------------------------------------
extern "C" void kernel_launch(void* const* d_in, const int* in_sizes, int n_in,
                              void* d_out, int out_size) {
    const float* q  = (const float*)d_in[0];
    const float* k  = (const float*)d_in[1];
    const float* v  = (const float*)d_in[2];
    const float* Wq = (const float*)d_in[3];
    const float* Wk = (const float*)d_in[4];
    const float* Wv = (const float*)d_in[5];
    const float* Wo = (const float*)d_in[6];
    // d_in[7] = W_bias: provably unused (exp(pos_bias - pos_bias) == 1)
    float* out = (float*)d_out;

    cudaFuncSetAttribute(hgemm<0>, cudaFuncAttributeMaxDynamicSharedMemorySize, SMEM_TOTAL);
    cudaFuncSetAttribute(hgemm<1>, cudaFuncAttributeMaxDynamicSharedMemorySize, SMEM_TOTAL);
    cudaFuncSetAttribute(hgemm<2>, cudaFuncAttributeMaxDynamicSharedMemorySize, SMEM_TOTAL);

    // all converts + num/den zeroing in one launch
    convert_all<<<TOT_CH / 256, 256>>>(q, k, v, Wq, Wk, Wv, Wo);

    // K, V projections (merged launch) -> fp16 Kph/Vph
    dim3 kvGrid(DD / 128, MTOT / 128, 2);   // (8, 64, 2)
    hgemm<0><<<kvGrid, 256, SMEM_TOTAL>>>(nullptr);

    // num/den over Kph, Vph
    dim3 redGrid(DD / 128, TT / 16);        // (8, 128)
    reduce_kernel<<<redGrid, 128>>>();

    // Q projection + fused sigmoid*num/den epilogue -> Yt (fp16)
    dim3 qGrid(DD / 128, MTOT / 128);       // (8, 64)
    hgemm<1><<<qGrid, 256, SMEM_TOTAL>>>(nullptr);

    // out = Yt @ Wo^T
    hgemm<2><<<qGrid, 256, SMEM_TOTAL>>>(out);
}

// round 12
// speedup vs baseline: 1.0001x; 1.0001x over previous
#include <cuda_runtime.h>
#include <cuda_fp16.h>
#include <cstdint>

// AFT-Full simplified: exp_pos_bias == 1  =>  num/den are per-(b,d) sums over t.
// out = ( sigmoid(q@WqT) * num/den ) @ WoT
// GEMMs: legacy mma.sync fp16 single-term, XOR-swizzled smem, BK=64.
// This round: 64x128 CTA tile, 32x32 warp tile (32 acc regs), 3 CTAs/SM
// (24 warps/SM) to hide MMA/ldsm latency across warps instead of within one.

#define BB 4
#define TT 2048
#define DD 1024
#define MTOT (BB * TT)   // 8192
#define KD 1024

// ---------------- scratch (static device globals) ----------------
__device__ __half g_qh[MTOT * KD];
__device__ __half g_kh[MTOT * KD];
__device__ __half g_vh[MTOT * KD];
__device__ __half g_Wqh[DD * KD], g_Wkh[DD * KD], g_Wvh[DD * KD], g_Woh[DD * KD];
__device__ __half g_Yth[MTOT * DD];
__device__ __half g_Kph[MTOT * DD];
__device__ __half g_Vph[MTOT * DD];
__device__ float g_num[BB * DD];
__device__ float g_den[BB * DD];

// ---------------- merged fp32 -> fp16 convert, all 7 tensors ----------------
constexpr int ACT_CH = MTOT * KD / 16;   // 524288 chunks of 16 floats
constexpr int W_CH   = DD * KD / 16;     // 65536
constexpr int TOT_CH = 3 * ACT_CH + 4 * W_CH;

__global__ __launch_bounds__(256) void convert_all(
    const float* __restrict__ q, const float* __restrict__ k, const float* __restrict__ v,
    const float* __restrict__ wq, const float* __restrict__ wk,
    const float* __restrict__ wv, const float* __restrict__ wo)
{
    const int i = blockIdx.x * blockDim.x + threadIdx.x;

    if (i < BB * DD) { g_num[i] = 0.0f; g_den[i] = 0.0f; }

    const float* src;
    __half* dst;
    size_t off;
    if (i < ACT_CH)              { src = q;  dst = g_qh;  off = i; }
    else if (i < 2 * ACT_CH)     { src = k;  dst = g_kh;  off = i - ACT_CH; }
    else if (i < 3 * ACT_CH)     { src = v;  dst = g_vh;  off = i - 2 * ACT_CH; }
    else {
        int w = i - 3 * ACT_CH;
        int t = w >> 16;
        off = w & 65535;
        if (t == 0)      { src = wq; dst = g_Wqh; }
        else if (t == 1) { src = wk; dst = g_Wkh; }
        else if (t == 2) { src = wv; dst = g_Wvh; }
        else             { src = wo; dst = g_Woh; }
    }

    const float4* s4 = (const float4*)(src) + off * 4;
    float4 x0 = s4[0], x1 = s4[1], x2 = s4[2], x3 = s4[3];
    float xs[16] = {x0.x, x0.y, x0.z, x0.w, x1.x, x1.y, x1.z, x1.w,
                    x2.x, x2.y, x2.z, x2.w, x3.x, x3.y, x3.z, x3.w};
    __half h[16];
#pragma unroll
    for (int j = 0; j < 16; j++) h[j] = __float2half(xs[j]);
    uint4* d4 = (uint4*)(dst + off * 16);
    d4[0] = *(uint4*)(h);
    d4[1] = *(uint4*)(h + 8);
}

// ---------------- PTX helpers ----------------
__device__ __forceinline__ void ldsm_x4(uint32_t& r0, uint32_t& r1, uint32_t& r2, uint32_t& r3, uint32_t addr) {
    asm volatile("ldmatrix.sync.aligned.m8n8.x4.shared.b16 {%0,%1,%2,%3}, [%4];"
                 : "=r"(r0), "=r"(r1), "=r"(r2), "=r"(r3) : "r"(addr));
}
__device__ __forceinline__ void mma_f16(float* d, const uint32_t* a, const uint32_t* b) {
    asm volatile("mma.sync.aligned.m16n8k16.row.col.f32.f16.f16.f32 "
                 "{%0,%1,%2,%3}, {%4,%5,%6,%7}, {%8,%9}, {%0,%1,%2,%3};"
                 : "+f"(d[0]), "+f"(d[1]), "+f"(d[2]), "+f"(d[3])
                 : "r"(a[0]), "r"(a[1]), "r"(a[2]), "r"(a[3]), "r"(b[0]), "r"(b[1]));
}
__device__ __forceinline__ void cp16(uint32_t s, const void* g) {
    asm volatile("cp.async.cg.shared.global [%0], [%1], 16;" :: "r"(s), "l"(g));
}
__device__ __forceinline__ void cp_commit() {
    asm volatile("cp.async.commit_group;" ::: "memory");
}
template <int N>
__device__ __forceinline__ void cp_wait() {
    asm volatile("cp.async.wait_group %0;" :: "n"(N) : "memory");
}

// ---------------- tensor-core GEMM: C[M,N] = A[M,K] @ B[N,K]^T ----------------
// BM=64, BN=128, BK=64, 3-stage cp.async, 256 threads (8 warps 2x4, warp 32x32),
// 3 CTAs/SM, Swizzle<3,4,3> smem (128B rows).
// MODE 0: K/V merged -> fp16. MODE 1: Q + fused sigmoid*ratio -> Yt.
// MODE 2: out = Yt @ Wo^T -> fp32.
constexpr int BM = 64;
constexpr int BK = 64;
constexpr int NT = KD / BK;              // 16 k-tiles
constexpr int A_T = BM * BK * 2;         // 8192 B
constexpr int B_T = 128 * BK * 2;        // 16384 B
constexpr int STAGE_B = A_T + B_T;       // 24576 B
constexpr int NSTAGE = 3;
constexpr int SMEM_TOTAL = NSTAGE * STAGE_B;  // 73728 B

template <int MODE>
__global__ __launch_bounds__(256, 3) void hgemm(float* __restrict__ Cout)
{
    extern __shared__ char smem[];
    const uint32_t sb = (uint32_t)__cvta_generic_to_shared(smem);

    const __half *A, *Bh;
    __half* Ch = nullptr;
    float* C = nullptr;
    if (MODE == 0) {
        if (blockIdx.z == 0) { A = g_kh; Bh = g_Wkh; Ch = g_Kph; }
        else                 { A = g_vh; Bh = g_Wvh; Ch = g_Vph; }
    } else if (MODE == 1) {
        A = g_qh; Bh = g_Wqh;
    } else {
        A = g_Yth; Bh = g_Woh; C = Cout;
    }

    const int tid = threadIdx.x;
    const int wid = tid >> 5, lane = tid & 31;
    const int rowBase = blockIdx.y * BM;
    const int colBase = blockIdx.x * 128;

    // 8 warps: 2 (M) x 4 (N); warp tile 32x32
    const int warpM = (wid >> 2) * 32;
    const int warpN = (wid & 3) * 32;

    const int aRowL = warpM + (lane & 15);
    const int aC16  = (lane >> 4);            // 0 or 1
    const int bRowL = warpN + ((lane >> 4) << 3) + (lane & 7);
    const int bC16  = ((lane >> 3) & 1);

    float acc[2][4][4];
#pragma unroll
    for (int m = 0; m < 2; m++)
#pragma unroll
        for (int n = 0; n < 4; n++)
#pragma unroll
            for (int r = 0; r < 4; r++) acc[m][n][r] = 0.0f;

    auto fill_stage = [&](int buf, int k0) {
        const uint32_t stg = sb + buf * STAGE_B;
#pragma unroll
        for (int i = 0; i < 2; i++) {   // A: 512 chunks of 16B, 2/thread
            const int ch = tid + i * 256;
            const int r = ch >> 3, c = ch & 7;
            const uint32_t so = (uint32_t)(r * 128 + ((c ^ (r & 7)) * 16));
            cp16(stg + so, A + (size_t)(rowBase + r) * KD + k0 + c * 8);
        }
#pragma unroll
        for (int i = 0; i < 4; i++) {   // B: 1024 chunks, 4/thread
            const int ch = tid + i * 256;
            const int r = ch >> 3, c = ch & 7;
            const uint32_t so = (uint32_t)(r * 128 + ((c ^ (r & 7)) * 16));
            cp16(stg + A_T + so, Bh + (size_t)(colBase + r) * KD + k0 + c * 8);
        }
        cp_commit();
    };

    fill_stage(0, 0);
    fill_stage(1, BK);

    for (int kt = 0; kt < NT; kt++) {
        if (kt < NT - 1) cp_wait<1>(); else cp_wait<0>();
        __syncthreads();

        if (kt + 2 < NT) fill_stage((kt + 2) % NSTAGE, (kt + 2) * BK);

        const uint32_t stg = sb + (kt % NSTAGE) * STAGE_B;
        const uint32_t sA = stg;
        const uint32_t sB = stg + A_T;

#pragma unroll
        for (int s = 0; s < 4; s++) {   // four k16 sub-steps per BK=64
            uint32_t a[2][4], b[4][2];
#pragma unroll
            for (int p = 0; p < 2; p++) {
                const int row = bRowL + p * 16;
                const int c16 = (s * 2 + bC16) ^ (row & 7);
                const uint32_t addr = sB + (uint32_t)(row * 128 + c16 * 16);
                ldsm_x4(b[2 * p][0], b[2 * p][1], b[2 * p + 1][0], b[2 * p + 1][1], addr);
            }
#pragma unroll
            for (int mf = 0; mf < 2; mf++) {
                const int row = aRowL + mf * 16;
                const int c16 = (s * 2 + aC16) ^ (row & 7);
                const uint32_t addr = sA + (uint32_t)(row * 128 + c16 * 16);
                ldsm_x4(a[mf][0], a[mf][1], a[mf][2], a[mf][3], addr);
            }
#pragma unroll
            for (int m = 0; m < 2; m++)
#pragma unroll
                for (int n = 0; n < 4; n++)
                    mma_f16(acc[m][n], a[m], b[n]);
        }
        __syncthreads();
    }

    // ---------------- epilogue ----------------
    const int er = rowBase + warpM + (lane >> 2);
    const int ec = colBase + warpN + (lane & 3) * 2;

    if (MODE == 1) {
        const int b = rowBase >> 11;
#pragma unroll
        for (int n = 0; n < 4; n++) {
            const int c = ec + n * 8;
            const float r0 = g_num[b * DD + c]     / g_den[b * DD + c];
            const float r1 = g_num[b * DD + c + 1] / g_den[b * DD + c + 1];
#pragma unroll
            for (int m = 0; m < 2; m++) {
#pragma unroll
                for (int h = 0; h < 2; h++) {
                    const int r = er + m * 16 + h * 8;
                    float y0 = r0 / (1.0f + __expf(-acc[m][n][h * 2]));
                    float y1 = r1 / (1.0f + __expf(-acc[m][n][h * 2 + 1]));
                    *(__half2*)(g_Yth + (size_t)r * DD + c) =
                        __floats2half2_rn(y0, y1);
                }
            }
        }
    } else if (MODE == 0) {
#pragma unroll
        for (int m = 0; m < 2; m++)
#pragma unroll
            for (int n = 0; n < 4; n++) {
                const int c = ec + n * 8;
#pragma unroll
                for (int h = 0; h < 2; h++) {
                    const int r = er + m * 16 + h * 8;
                    *(__half2*)(Ch + (size_t)r * DD + c) =
                        __floats2half2_rn(acc[m][n][h * 2], acc[m][n][h * 2 + 1]);
                }
            }
    } else {
#pragma unroll
        for (int m = 0; m < 2; m++)
#pragma unroll
            for (int n = 0; n < 4; n++) {
                const int c = ec + n * 8;
#pragma unroll
                for (int h = 0; h < 2; h++) {
                    const int r = er + m * 16 + h * 8;
                    *(float2*)(C + (size_t)r * DD + c) =
                        make_float2(acc[m][n][h * 2], acc[m][n][h * 2 + 1]);
                }
            }
    }
}

// ---------------- num/den reduction (fp16 inputs) ----------------
__global__ __launch_bounds__(128) void reduce_kernel() {
    const int d  = blockIdx.x * 128 + threadIdx.x;
    const int t0 = blockIdx.y * 16;

    float num0 = 0.f, num1 = 0.f, num2 = 0.f, num3 = 0.f;
    float den0 = 0.f, den1 = 0.f, den2 = 0.f, den3 = 0.f;

#pragma unroll 4
    for (int t = t0; t < t0 + 16; t++) {
        const size_t off = (size_t)t * DD + d;
        float k0 = __half2float(g_Kph[off + (size_t)0 * TT * DD]);
        float k1 = __half2float(g_Kph[off + (size_t)1 * TT * DD]);
        float k2 = __half2float(g_Kph[off + (size_t)2 * TT * DD]);
        float k3 = __half2float(g_Kph[off + (size_t)3 * TT * DD]);
        float m = fmaxf(fmaxf(k0, k1), fmaxf(k2, k3));
        float e0 = __expf(k0 - m);
        float e1 = __expf(k1 - m);
        float e2 = __expf(k2 - m);
        float e3 = __expf(k3 - m);
        float v0 = __half2float(g_Vph[off + (size_t)0 * TT * DD]);
        float v1 = __half2float(g_Vph[off + (size_t)1 * TT * DD]);
        float v2 = __half2float(g_Vph[off + (size_t)2 * TT * DD]);
        float v3 = __half2float(g_Vph[off + (size_t)3 * TT * DD]);
        num0 = fmaf(e0, v0, num0);  den0 += e0;
        num1 = fmaf(e1, v1, num1);  den1 += e1;
        num2 = fmaf(e2, v2, num2);  den2 += e2;
        num3 = fmaf(e3, v3, num3);  den3 += e3;
    }

    atomicAdd(&g_num[0 * DD + d], num0);
    atomicAdd(&g_num[1 * DD + d], num1);
    atomicAdd(&g_num[2 * DD + d], num2);
    atomicAdd(&g_num[3 * DD + d], num3);
    atomicAdd(&g_den[0 * DD + d], den0);
    atomicAdd(&g_den[1 * DD + d], den1);
    atomicAdd(&g_den[2 * DD + d], den2);
    atomicAdd(&g_den[3 * DD + d], den3);
}

// ---------------------------------------------------------------------------
extern "C" void kernel_launch(void* const* d_in, const int* in_sizes, int n_in,
                              void* d_out, int out_size) {
    const float* q  = (const float*)d_in[0];
    const float* k  = (const float*)d_in[1];
    const float* v  = (const float*)d_in[2];
    const float* Wq = (const float*)d_in[3];
    const float* Wk = (const float*)d_in[4];
    const float* Wv = (const float*)d_in[5];
    const float* Wo = (const float*)d_in[6];
    // d_in[7] = W_bias: provably unused (exp(pos_bias - pos_bias) == 1)
    float* out = (float*)d_out;

    cudaFuncSetAttribute(hgemm<0>, cudaFuncAttributeMaxDynamicSharedMemorySize, SMEM_TOTAL);
    cudaFuncSetAttribute(hgemm<1>, cudaFuncAttributeMaxDynamicSharedMemorySize, SMEM_TOTAL);
    cudaFuncSetAttribute(hgemm<2>, cudaFuncAttributeMaxDynamicSharedMemorySize, SMEM_TOTAL);

    // all converts + num/den zeroing in one launch
    convert_all<<<TOT_CH / 256, 256>>>(q, k, v, Wq, Wk, Wv, Wo);

    // K, V projections (merged launch) -> fp16 Kph/Vph
    dim3 kvGrid(DD / 128, MTOT / BM, 2);    // (8, 128, 2)
    hgemm<0><<<kvGrid, 256, SMEM_TOTAL>>>(nullptr);

    // num/den over Kph, Vph
    dim3 redGrid(DD / 128, TT / 16);        // (8, 128)
    reduce_kernel<<<redGrid, 128>>>();

    // Q projection + fused sigmoid*num/den epilogue -> Yt (fp16)
    dim3 qGrid(DD / 128, MTOT / BM);        // (8, 128)
    hgemm<1><<<qGrid, 256, SMEM_TOTAL>>>(nullptr);

    // out = Yt @ Wo^T
    hgemm<2><<<qGrid, 256, SMEM_TOTAL>>>(out);
}